// round 9
// baseline (speedup 1.0000x reference)
#include <cuda_runtime.h>
#include <cuda_bf16.h>
#include <math.h>

// Problem constants
#define T_STEPS 512
#define BATCH   128
#define DIN     256
#define HID     256
#define GATES   1024            // 4*HID
#define NCOLS   2048            // both directions stacked
#define MROWS   65536           // T*B
#define OUT_TB_STRIDE 512       // out row stride (2H)
#define OUT_MAIN (T_STEPS*BATCH*OUT_TB_STRIDE)  // 33,554,432

#define NTHR     64             // threads per persistent block
#define GRP_BLKS 16             // blocks per (dir,bgrp) sync group
#define GEMM_BLKS_PER_T 16      // gemm blocks contributing to one t

// Scratch: xg for both directions [MROWS x NCOLS] fp32 (536 MB)
__device__ float g_xg[(size_t)MROWS * NCOLS];
// per-(dir,bgrp,step) arrival counters for the recurrence barrier
__device__ int g_bar[2][8][T_STEPS];
// per-timestep xg readiness counters (gemm -> recurrence handshake)
__device__ int g_xg_ready[T_STEPS];
// compact ping-pong h state [dir][buf][batch][hid]
__device__ float g_h[2][2][BATCH][HID];

// ---- packed fp32x2 helpers (Blackwell FFMA2 path) -------------------------
#define PACK2(d, lo, hi) \
    asm("mov.b64 %0, {%1, %2};" : "=l"(d) : "f"(lo), "f"(hi))
#define UNPACK2(lo, hi, s) \
    asm("mov.b64 {%0, %1}, %2;" : "=f"(lo), "=f"(hi) : "l"(s))
#define FMA2(d, a, b) \
    asm("fma.rn.f32x2 %0, %1, %2, %0;" : "+l"(d) : "l"(a), "l"(b))

// ---------------------------------------------------------------------------
// Phase 1: xg = X @ Wcat^T + (b_ih + b_hh)   (classic 128x128x16 SGEMM)
// bm is remapped to t interleaved from both ends so both directions of the
// concurrent recurrence get their next timestep early.
// ---------------------------------------------------------------------------
__global__ __launch_bounds__(256) void gemm_xg_kernel(
    const float* __restrict__ X,
    const float* __restrict__ Wf, const float* __restrict__ Wb,
    const float* __restrict__ bif, const float* __restrict__ bhf,
    const float* __restrict__ bib, const float* __restrict__ bhb)
{
    const int bn = blockIdx.x;     // 0..15
    const int bm = blockIdx.y;     // 0..511
    const int t  = (bm & 1) ? (T_STEPS - 1 - (bm >> 1)) : (bm >> 1);
    const bool fwd = (bn < 8);
    const float* W  = fwd ? (Wf + (size_t)bn * 128 * DIN)
                          : (Wb + (size_t)(bn - 8) * 128 * DIN);
    const float* bi = fwd ? bif : bib;
    const float* bh = fwd ? bhf : bhb;
    const int nloc_base = (fwd ? bn : bn - 8) * 128;

    __shared__ float As[16][132];
    __shared__ float Bs[16][132];

    const int tid = threadIdx.x;
    const int tx = tid & 15, ty = tid >> 4;

    float acc[8][8];
    #pragma unroll
    for (int i = 0; i < 8; i++)
        #pragma unroll
        for (int j = 0; j < 8; j++) acc[i][j] = 0.f;

    const int loadRow = tid >> 2;          // 0..63
    const int loadK4  = (tid & 3) * 4;     // 0,4,8,12
    const float* Abase = X + (size_t)t * 128 * DIN;

    for (int k0 = 0; k0 < DIN; k0 += 16) {
        #pragma unroll
        for (int r = 0; r < 2; r++) {
            int row = loadRow + r * 64;
            float4 va = *(const float4*)(Abase + (size_t)row * DIN + k0 + loadK4);
            As[loadK4 + 0][row] = va.x; As[loadK4 + 1][row] = va.y;
            As[loadK4 + 2][row] = va.z; As[loadK4 + 3][row] = va.w;
            float4 vb = *(const float4*)(W + (size_t)row * DIN + k0 + loadK4);
            Bs[loadK4 + 0][row] = vb.x; Bs[loadK4 + 1][row] = vb.y;
            Bs[loadK4 + 2][row] = vb.z; Bs[loadK4 + 3][row] = vb.w;
        }
        __syncthreads();
        #pragma unroll
        for (int k = 0; k < 16; k++) {
            float a[8], b[8];
            float4 a0 = *(const float4*)&As[k][ty * 8];
            float4 a1 = *(const float4*)&As[k][ty * 8 + 4];
            float4 b0 = *(const float4*)&Bs[k][tx * 8];
            float4 b1 = *(const float4*)&Bs[k][tx * 8 + 4];
            a[0]=a0.x; a[1]=a0.y; a[2]=a0.z; a[3]=a0.w;
            a[4]=a1.x; a[5]=a1.y; a[6]=a1.z; a[7]=a1.w;
            b[0]=b0.x; b[1]=b0.y; b[2]=b0.z; b[3]=b0.w;
            b[4]=b1.x; b[5]=b1.y; b[6]=b1.z; b[7]=b1.w;
            #pragma unroll
            for (int i = 0; i < 8; i++)
                #pragma unroll
                for (int j = 0; j < 8; j++)
                    acc[i][j] += a[i] * b[j];
        }
        __syncthreads();
    }

    #pragma unroll
    for (int j = 0; j < 8; j++) {
        int nloc = tx * 8 + j;
        float bv = bi[nloc_base + nloc] + bh[nloc_base + nloc];
        int ncol = bn * 128 + nloc;
        #pragma unroll
        for (int i = 0; i < 8; i++) {
            int m = t * 128 + ty * 8 + i;
            g_xg[(size_t)m * NCOLS + ncol] = acc[i][j] + bv;
        }
    }

    // publish: this tile of xg[t] is ready
    __threadfence();
    __syncthreads();
    if (tid == 0) atomicAdd(&g_xg_ready[t], 1);
}

// ---------------------------------------------------------------------------
// init: zero counters, copy h0 into ping-pong buffer slot 1
// (step 0 reads buffer (0+1)&1 = 1)
// ---------------------------------------------------------------------------
__global__ void init_misc_kernel(const float* __restrict__ h0)
{
    int i = blockIdx.x * 256 + threadIdx.x;   // 0..65535
    int dir = i >> 15;
    int rem = i & 32767;                       // b*HID + j
    ((float*)g_h)[dir * 65536 + 32768 + rem] = h0[i];
    if (i < 2 * 8 * T_STEPS) ((int*)g_bar)[i] = 0;
    if (i < T_STEPS) g_xg_ready[i] = 0;
}

// ---------------------------------------------------------------------------
// Persistent recurrence kernel.
// grid = 256 blocks: blk = dir*128 + bgrp*16 + jgrp
// 64 threads: jl = tid&15 (one j), bp = tid>>4 (quad of batches).
// Thread tile: 4 gates x 1 j x 4 batches, fp32x2-packed accumulators.
// h state ping-pongs through compact L2-resident g_h buffers.
// ---------------------------------------------------------------------------
__device__ __forceinline__ float sigm(float x) { return 1.f / (1.f + expf(-x)); }

#define WS_STRIDE 260           // floats per row (65 float4)
#define SMEM_FLOATS (64*WS_STRIDE + 16*WS_STRIDE)
#define SMEM_BYTES  (SMEM_FLOATS * 4)

extern "C" __global__ void __launch_bounds__(NTHR) lstm_persist_kernel(
    const float* __restrict__ Whh_f, const float* __restrict__ Whh_b,
    const float* __restrict__ c0, float* __restrict__ out)
{
    extern __shared__ float smem[];
    float* Ws = smem;                      // [64][WS_STRIDE]  rows r=g*16+jl
    float* hs = smem + 64 * WS_STRIDE;     // [16][WS_STRIDE]

    const int blk  = blockIdx.x;
    const int dir  = blk >> 7;
    const int bgrp = (blk >> 4) & 7;
    const int jgrp = blk & 15;
    const int tid  = threadIdx.x;
    const int jl   = tid & 15;
    const int bp   = tid >> 4;             // 0..3
    const int j    = jgrp * 16 + jl;
    const int b0   = bgrp * 16 + bp * 4;   // 4 consecutive batches

    const float* Whh = dir ? Whh_b : Whh_f;

    // Load W_hh slice once: row r = g*16+jj -> Whh[g*256 + jgrp*16 + jj][k]
    for (int i = tid; i < 64 * 64; i += NTHR) {      // float4 granularity
        int r  = i >> 6;
        int kq = i & 63;
        int g = r >> 4, jj = r & 15;
        float4 v = *(const float4*)(Whh + ((size_t)(g * 256 + jgrp * 16 + jj)) * HID + kq * 4);
        *(float4*)(Ws + r * WS_STRIDE + kq * 4) = v;
    }

    // cell state in registers for the whole recurrence
    float cr[4];
    #pragma unroll
    for (int c = 0; c < 4; c++)
        cr[c] = c0[(size_t)dir * BATCH * HID + (size_t)(b0 + c) * HID + j];

    __syncthreads();

    const float4* w0p = (const float4*)(Ws + (0 * 16 + jl) * WS_STRIDE);
    const float4* w1p = (const float4*)(Ws + (1 * 16 + jl) * WS_STRIDE);
    const float4* w2p = (const float4*)(Ws + (2 * 16 + jl) * WS_STRIDE);
    const float4* w3p = (const float4*)(Ws + (3 * 16 + jl) * WS_STRIDE);
    const float4* hp0 = (const float4*)(hs + (bp * 4 + 0) * WS_STRIDE);
    const float4* hp1 = (const float4*)(hs + (bp * 4 + 1) * WS_STRIDE);
    const float4* hp2 = (const float4*)(hs + (bp * 4 + 2) * WS_STRIDE);
    const float4* hp3 = (const float4*)(hs + (bp * 4 + 3) * WS_STRIDE);

    for (int s = 0; s < T_STEPS; s++) {
        const int t = dir ? (T_STEPS - 1 - s) : s;

        // ---- wait: xg[t] ready (gemm branch) + siblings done step s-1 ----
        if (tid == 0) {
            volatile int* px = &g_xg_ready[t];
            while (*px < GEMM_BLKS_PER_T) __nanosleep(32);
            if (s > 0) {
                volatile int* p = &g_bar[dir][bgrp][s - 1];
                while (*p < GRP_BLKS) __nanosleep(32);
            }
        }
        __syncthreads();

        // ---- prefetch this thread's xg contributions ----
        float xi[4], xf[4], xg[4], xo[4];
        {
            const float* xgp = g_xg + ((size_t)t * BATCH + b0) * NCOLS + dir * GATES + j;
            #pragma unroll
            for (int c = 0; c < 4; c++) {
                xi[c] = xgp[0]; xf[c] = xgp[256]; xg[c] = xgp[512]; xo[c] = xgp[768];
                xgp += NCOLS;
            }
        }

        // ---- stage h_prev slice [16 batches x 256] from ping-pong buffer ----
        {
            const float* hp = &g_h[dir][(s + 1) & 1][bgrp * 16][0];
            #pragma unroll
            for (int i = 0; i < 16; i++) {
                int lin = i * NTHR + tid;      // 0..1023
                int bb = lin >> 6, kq = lin & 63;
                float4 v = __ldcv((const float4*)(hp + (size_t)bb * HID + kq * 4));
                *(float4*)(hs + bb * WS_STRIDE + kq * 4) = v;
            }
        }
        __syncthreads();

        // ---- GEMM fragment: 4 gates x 1 j x 4 batches, fp32x2 packed ----
        unsigned long long acc[4][2];
        #pragma unroll
        for (int g = 0; g < 4; g++) {
            float z = 0.f;
            PACK2(acc[g][0], z, z);
            PACK2(acc[g][1], z, z);
        }

        #pragma unroll 4
        for (int kq = 0; kq < 64; kq++) {
            float4 w0 = w0p[kq], w1 = w1p[kq], w2 = w2p[kq], w3 = w3p[kq];
            float4 ha = hp0[kq], hb = hp1[kq], hc = hp2[kq], hd = hp3[kq];

            #define K_STEP(E)                                                \
            {                                                                \
                unsigned long long hlo, hhi, wp;                             \
                PACK2(hlo, ha.E, hb.E);                                      \
                PACK2(hhi, hc.E, hd.E);                                      \
                PACK2(wp, w0.E, w0.E);                                       \
                FMA2(acc[0][0], wp, hlo); FMA2(acc[0][1], wp, hhi);          \
                PACK2(wp, w1.E, w1.E);                                       \
                FMA2(acc[1][0], wp, hlo); FMA2(acc[1][1], wp, hhi);          \
                PACK2(wp, w2.E, w2.E);                                       \
                FMA2(acc[2][0], wp, hlo); FMA2(acc[2][1], wp, hhi);          \
                PACK2(wp, w3.E, w3.E);                                       \
                FMA2(acc[3][0], wp, hlo); FMA2(acc[3][1], wp, hhi);          \
            }
            K_STEP(x) K_STEP(y) K_STEP(z) K_STEP(w)
            #undef K_STEP
        }

        // ---- unpack, fused gate math, h/c update ----
        float gi[4], gf[4], gg[4], go[4];
        UNPACK2(gi[0], gi[1], acc[0][0]); UNPACK2(gi[2], gi[3], acc[0][1]);
        UNPACK2(gf[0], gf[1], acc[1][0]); UNPACK2(gf[2], gf[3], acc[1][1]);
        UNPACK2(gg[0], gg[1], acc[2][0]); UNPACK2(gg[2], gg[3], acc[2][1]);
        UNPACK2(go[0], go[1], acc[3][0]); UNPACK2(go[2], go[3], acc[3][1]);

        float* orow = out + (size_t)t * BATCH * OUT_TB_STRIDE + dir * HID + j;
        float* hrow = &g_h[dir][s & 1][0][0] + j;
        float hn[4], cn[4];
        #pragma unroll
        for (int c = 0; c < 4; c++) {
            float Gi = gi[c] + xi[c], Gf = gf[c] + xf[c];
            float Gg = gg[c] + xg[c], Go = go[c] + xo[c];
            cn[c] = sigm(Gf) * cr[c] + sigm(Gi) * tanhf(Gg);
            hn[c] = sigm(Go) * tanhf(cn[c]);
            cr[c] = cn[c];
            orow[(size_t)(b0 + c) * OUT_TB_STRIDE] = hn[c];
            hrow[(size_t)(b0 + c) * HID]           = hn[c];
        }

        // final step: also write hT / cT tails
        if (s == T_STEPS - 1) {
            float* tail_h = out + OUT_MAIN + dir * 65536;          // hf or hb
            float* tail_c = tail_h + 32768;                         // cf or cb
            #pragma unroll
            for (int c = 0; c < 4; c++) {
                tail_h[(b0 + c) * HID + j] = hn[c];
                tail_c[(b0 + c) * HID + j] = cn[c];
            }
        }

        // ---- publish h for step s (release: fence then arrive) ----
        __threadfence();
        __syncthreads();
        if (tid == 0) atomicAdd(&g_bar[dir][bgrp][s], 1);
    }
}

// ---------------------------------------------------------------------------
extern "C" void kernel_launch(void* const* d_in, const int* in_sizes, int n_in,
                              void* d_out, int out_size)
{
    const float* x     = (const float*)d_in[0];
    const float* h0    = (const float*)d_in[1];
    const float* c0    = (const float*)d_in[2];
    const float* Wih_f = (const float*)d_in[3];
    const float* Whh_f = (const float*)d_in[4];
    const float* bih_f = (const float*)d_in[5];
    const float* bhh_f = (const float*)d_in[6];
    const float* Wih_b = (const float*)d_in[7];
    const float* Whh_b = (const float*)d_in[8];
    const float* bih_b = (const float*)d_in[9];
    const float* bhh_b = (const float*)d_in[10];
    float* out = (float*)d_out;

    // side stream + events for the fork-join graph branch (created once;
    // must outlive graph capture, so never destroyed)
    static cudaStream_t s_gemm = nullptr;
    static cudaEvent_t ev_fork = nullptr, ev_join = nullptr;
    if (!s_gemm) {
        cudaStreamCreateWithFlags(&s_gemm, cudaStreamNonBlocking);
        cudaEventCreateWithFlags(&ev_fork, cudaEventDisableTiming);
        cudaEventCreateWithFlags(&ev_join, cudaEventDisableTiming);
    }

    cudaFuncSetAttribute(lstm_persist_kernel,
                         cudaFuncAttributeMaxDynamicSharedMemorySize, SMEM_BYTES);

    // main (capture) stream: init counters + h0 copy
    init_misc_kernel<<<256, 256>>>(h0);

    // fork: gemm branch runs concurrently with the persistent recurrence
    cudaEventRecord(ev_fork, 0);
    cudaStreamWaitEvent(s_gemm, ev_fork, 0);
    gemm_xg_kernel<<<dim3(16, 512), 256, 0, s_gemm>>>(
        x, Wih_f, Wih_b, bih_f, bhh_f, bih_b, bhh_b);
    cudaEventRecord(ev_join, s_gemm);

    // main stream: persistent recurrence (consumes xg as it becomes ready)
    lstm_persist_kernel<<<256, NTHR, SMEM_BYTES>>>(Whh_f, Whh_b, c0, out);

    // join
    cudaStreamWaitEvent(0, ev_join, 0);
}

// round 11
// speedup vs baseline: 1.0847x; 1.0847x over previous
#include <cuda_runtime.h>
#include <cuda_bf16.h>
#include <math.h>
#include <stdint.h>

// Problem constants
#define T_STEPS 512
#define BATCH   128
#define DIN     256
#define HID     256
#define NCOLS   2048            // dir*1024 + gate*256 + j
#define OUT_TB_STRIDE 512
#define OUT_MAIN (T_STEPS*BATCH*OUT_TB_STRIDE)

#define CTAS_PER_DIR 32
#define GEMM_BLKS_PER_T 16

// xg scratch, layout [t][ncol(2048)][b(128)] fp32 (536 MB)
__device__ float g_xg[(size_t)T_STEPS * NCOLS * BATCH];
// h ping-pong, bf16 hi/lo planes: [dir][buf][hilo][b(128)][k(256)]
__device__ __nv_bfloat16 g_hbf[2][2][2][BATCH][HID];
// sync counters
__device__ int g_bar[2][T_STEPS];
__device__ int g_xg_ready[T_STEPS];

__device__ __forceinline__ float sigm(float x) { return 1.f / (1.f + expf(-x)); }

// mma.sync m16n8k16 row.col f32.bf16.bf16.f32  (baseline PTX, sm_80+)
__device__ __forceinline__ void mma_bf16(float* d, const uint32_t* a, const uint32_t* b) {
    asm volatile(
        "mma.sync.aligned.m16n8k16.row.col.f32.bf16.bf16.f32 "
        "{%0,%1,%2,%3}, {%4,%5,%6,%7}, {%8,%9}, {%0,%1,%2,%3};"
        : "+f"(d[0]), "+f"(d[1]), "+f"(d[2]), "+f"(d[3])
        : "r"(a[0]), "r"(a[1]), "r"(a[2]), "r"(a[3]), "r"(b[0]), "r"(b[1]));
}

// ---------------------------------------------------------------------------
// Phase 1: xg = X @ Wcat^T + (b_ih + b_hh), written as [t][ncol][b].
// bm interleaved from both ends so both recurrence directions are fed early.
// ---------------------------------------------------------------------------
__global__ __launch_bounds__(256) void gemm_xg_kernel(
    const float* __restrict__ X,
    const float* __restrict__ Wf, const float* __restrict__ Wb,
    const float* __restrict__ bif, const float* __restrict__ bhf,
    const float* __restrict__ bib, const float* __restrict__ bhb)
{
    const int bn = blockIdx.x;     // 0..15
    const int bm = blockIdx.y;     // 0..511
    const int t  = (bm & 1) ? (T_STEPS - 1 - (bm >> 1)) : (bm >> 1);
    const bool fwd = (bn < 8);
    const float* W  = fwd ? (Wf + (size_t)bn * 128 * DIN)
                          : (Wb + (size_t)(bn - 8) * 128 * DIN);
    const float* bi = fwd ? bif : bib;
    const float* bh = fwd ? bhf : bhb;
    const int nloc_base = (fwd ? bn : bn - 8) * 128;

    __shared__ float As[16][132];
    __shared__ float Bs[16][132];

    const int tid = threadIdx.x;
    const int tx = tid & 15, ty = tid >> 4;

    float acc[8][8];
    #pragma unroll
    for (int i = 0; i < 8; i++)
        #pragma unroll
        for (int j = 0; j < 8; j++) acc[i][j] = 0.f;

    const int loadRow = tid >> 2;
    const int loadK4  = (tid & 3) * 4;
    const float* Abase = X + (size_t)t * 128 * DIN;

    for (int k0 = 0; k0 < DIN; k0 += 16) {
        #pragma unroll
        for (int r = 0; r < 2; r++) {
            int row = loadRow + r * 64;
            float4 va = *(const float4*)(Abase + (size_t)row * DIN + k0 + loadK4);
            As[loadK4 + 0][row] = va.x; As[loadK4 + 1][row] = va.y;
            As[loadK4 + 2][row] = va.z; As[loadK4 + 3][row] = va.w;
            float4 vb = *(const float4*)(W + (size_t)row * DIN + k0 + loadK4);
            Bs[loadK4 + 0][row] = vb.x; Bs[loadK4 + 1][row] = vb.y;
            Bs[loadK4 + 2][row] = vb.z; Bs[loadK4 + 3][row] = vb.w;
        }
        __syncthreads();
        #pragma unroll
        for (int k = 0; k < 16; k++) {
            float a[8], b[8];
            float4 a0 = *(const float4*)&As[k][ty * 8];
            float4 a1 = *(const float4*)&As[k][ty * 8 + 4];
            float4 b0 = *(const float4*)&Bs[k][tx * 8];
            float4 b1 = *(const float4*)&Bs[k][tx * 8 + 4];
            a[0]=a0.x; a[1]=a0.y; a[2]=a0.z; a[3]=a0.w;
            a[4]=a1.x; a[5]=a1.y; a[6]=a1.z; a[7]=a1.w;
            b[0]=b0.x; b[1]=b0.y; b[2]=b0.z; b[3]=b0.w;
            b[4]=b1.x; b[5]=b1.y; b[6]=b1.z; b[7]=b1.w;
            #pragma unroll
            for (int i = 0; i < 8; i++)
                #pragma unroll
                for (int j = 0; j < 8; j++)
                    acc[i][j] += a[i] * b[j];
        }
        __syncthreads();
    }

    #pragma unroll
    for (int j = 0; j < 8; j++) {
        int nloc = tx * 8 + j;
        float bv = bi[nloc_base + nloc] + bh[nloc_base + nloc];
        int ncol = bn * 128 + nloc;
        float* base = g_xg + ((size_t)t * NCOLS + ncol) * BATCH + ty * 8;
        *(float4*)(base)     = make_float4(acc[0][j]+bv, acc[1][j]+bv, acc[2][j]+bv, acc[3][j]+bv);
        *(float4*)(base + 4) = make_float4(acc[4][j]+bv, acc[5][j]+bv, acc[6][j]+bv, acc[7][j]+bv);
    }

    __threadfence();
    __syncthreads();
    if (tid == 0) atomicAdd(&g_xg_ready[t], 1);
}

// ---------------------------------------------------------------------------
// init: zero counters; h0 -> g_hbf buf 1 (step 0 reads buf (0+1)&1 = 1)
// grid 128 x 256 = 32768 threads, one per (dir,b,j/2)... use one per element.
// ---------------------------------------------------------------------------
__global__ void init_misc_kernel(const float* __restrict__ h0)
{
    int i = blockIdx.x * 256 + threadIdx.x;   // 0..65535 (grid 256)
    int dir = i >> 15;
    int rem = i & 32767;                       // b*HID + k
    float h = h0[i];
    __nv_bfloat16 hh = __float2bfloat16(h);
    __nv_bfloat16 hl = __float2bfloat16(h - __bfloat162float(hh));
    ((__nv_bfloat16*)g_hbf)[((size_t)(dir * 2 + 1) * 2 + 0) * 32768 + rem] = hh;
    ((__nv_bfloat16*)g_hbf)[((size_t)(dir * 2 + 1) * 2 + 1) * 32768 + rem] = hl;
    if (i < 2 * T_STEPS) ((int*)g_bar)[i] = 0;
    if (i < T_STEPS) g_xg_ready[i] = 0;
}

// ---------------------------------------------------------------------------
// Persistent HMMA recurrence.
// grid = 64 CTAs: dir = blk>>5, q = blk&31 owns j in [q*8, q*8+8).
// 128 threads = 4 warps; warp w owns batches [w*32, w*32+32).
// Per-CTA gates GEMM: M=128 (batch), N=32 (4 gates x 8 j), K=256,
// computed as bf16x3 (Ah*Bh + Al*Bh + Ah*Bl), fp32 accum, D init = xg.
// ---------------------------------------------------------------------------
#define HS_STRIDE 264                       // bf16 elements per padded row
#define HS_ELEMS  (128 * HS_STRIDE)         // one h plane
#define WS_ELEMS  (32 * HS_STRIDE)          // one W plane
#define SMEM_TOTAL ((2 * HS_ELEMS + 2 * WS_ELEMS) * 2)

extern "C" __global__ void __launch_bounds__(128) lstm_mma_kernel(
    const float* __restrict__ Whh_f, const float* __restrict__ Whh_b,
    const float* __restrict__ c0, float* __restrict__ out)
{
    extern __shared__ __nv_bfloat16 smem[];
    __nv_bfloat16* hs_hi = smem;
    __nv_bfloat16* hs_lo = smem + HS_ELEMS;
    __nv_bfloat16* ws_hi = smem + 2 * HS_ELEMS;
    __nv_bfloat16* ws_lo = smem + 2 * HS_ELEMS + WS_ELEMS;

    const int blk = blockIdx.x;
    const int dir = blk >> 5;
    const int q   = blk & 31;
    const int tid = threadIdx.x;
    const int w   = tid >> 5;               // warp
    const int ln  = tid & 31;
    const int grp = ln >> 2;                // groupID 0..7
    const int tig = ln & 3;                 // thread-in-group

    const float* Whh = dir ? Whh_b : Whh_f;

    // ---- load W_hh slice (32 rows: n = g*8+jj -> wrow = g*256 + q*8 + jj) ----
    for (int i = tid; i < 32 * HID; i += 128) {
        int n = i >> 8, k = i & 255;
        int wrow = (n >> 3) * HID + q * 8 + (n & 7);
        float wv = Whh[(size_t)wrow * HID + k];
        __nv_bfloat16 wh = __float2bfloat16(wv);
        ws_hi[n * HS_STRIDE + k] = wh;
        ws_lo[n * HS_STRIDE + k] = __float2bfloat16(wv - __bfloat162float(wh));
    }

    // ---- cell state in registers: 8 cells = (2 mt) x (2 row) x (2 jj) ----
    float cr[8];
    #pragma unroll
    for (int mt = 0; mt < 2; mt++)
        #pragma unroll
        for (int rr = 0; rr < 2; rr++)
            #pragma unroll
            for (int jb = 0; jb < 2; jb++) {
                int b = w * 32 + mt * 16 + grp + rr * 8;
                int j = q * 8 + tig * 2 + jb;
                cr[mt * 4 + rr * 2 + jb] =
                    c0[(size_t)dir * BATCH * HID + (size_t)b * HID + j];
            }

    __syncthreads();

    for (int s = 0; s < T_STEPS; s++) {
        const int t = dir ? (T_STEPS - 1 - s) : s;

        // ---- wait: xg[t] produced + all CTAs of this dir done step s-1 ----
        if (tid == 0) {
            volatile int* px = &g_xg_ready[t];
            while (*px < GEMM_BLKS_PER_T) __nanosleep(64);
            if (s > 0) {
                volatile int* p = &g_bar[dir][s - 1];
                while (*p < CTAS_PER_DIR) __nanosleep(32);
            }
        }
        __syncthreads();     // also guards hs reuse vs previous step readers

        // ---- stage h planes [128 x 256] bf16 into padded SMEM ----
        {
            const uint4* src_hi = (const uint4*)&g_hbf[dir][(s + 1) & 1][0][0][0];
            const uint4* src_lo = (const uint4*)&g_hbf[dir][(s + 1) & 1][1][0][0];
            #pragma unroll
            for (int i = tid; i < 4096; i += 128) {     // uint4 = 8 bf16
                int b = i >> 5, kq = i & 31;
                uint4 vh = __ldcv(src_hi + i);
                uint4 vl = __ldcv(src_lo + i);
                *(uint4*)&hs_hi[b * HS_STRIDE + kq * 8] = vh;
                *(uint4*)&hs_lo[b * HS_STRIDE + kq * 8] = vl;
            }
        }

        // ---- D init = xg fragments ----
        float acc[2][4][4];
        {
            #pragma unroll
            for (int mt = 0; mt < 2; mt++)
                #pragma unroll
                for (int nt = 0; nt < 4; nt++)
                    #pragma unroll
                    for (int rr = 0; rr < 2; rr++)
                        #pragma unroll
                        for (int jb = 0; jb < 2; jb++) {
                            int b = w * 32 + mt * 16 + grp + rr * 8;
                            int ncol = dir * 1024 + nt * 256 + q * 8 + tig * 2 + jb;
                            acc[mt][nt][rr * 2 + jb] =
                                __ldcg(g_xg + ((size_t)t * NCOLS + ncol) * BATCH + b);
                        }
        }
        __syncthreads();

        // ---- K loop: 16 k-tiles x (2 mt x 4 nt) x 3 passes ----
        #pragma unroll 4
        for (int kt = 0; kt < 16; kt++) {
            const int k0 = kt * 16 + tig * 2;
            uint32_t Ah[2][4], Al[2][4], Bh[4][2], Bl[4][2];
            #pragma unroll
            for (int mt = 0; mt < 2; mt++) {
                int b = w * 32 + mt * 16 + grp;
                Ah[mt][0] = *(const uint32_t*)&hs_hi[(b    ) * HS_STRIDE + k0];
                Ah[mt][1] = *(const uint32_t*)&hs_hi[(b + 8) * HS_STRIDE + k0];
                Ah[mt][2] = *(const uint32_t*)&hs_hi[(b    ) * HS_STRIDE + k0 + 8];
                Ah[mt][3] = *(const uint32_t*)&hs_hi[(b + 8) * HS_STRIDE + k0 + 8];
                Al[mt][0] = *(const uint32_t*)&hs_lo[(b    ) * HS_STRIDE + k0];
                Al[mt][1] = *(const uint32_t*)&hs_lo[(b + 8) * HS_STRIDE + k0];
                Al[mt][2] = *(const uint32_t*)&hs_lo[(b    ) * HS_STRIDE + k0 + 8];
                Al[mt][3] = *(const uint32_t*)&hs_lo[(b + 8) * HS_STRIDE + k0 + 8];
            }
            #pragma unroll
            for (int nt = 0; nt < 4; nt++) {
                int n = nt * 8 + grp;
                Bh[nt][0] = *(const uint32_t*)&ws_hi[n * HS_STRIDE + k0];
                Bh[nt][1] = *(const uint32_t*)&ws_hi[n * HS_STRIDE + k0 + 8];
                Bl[nt][0] = *(const uint32_t*)&ws_lo[n * HS_STRIDE + k0];
                Bl[nt][1] = *(const uint32_t*)&ws_lo[n * HS_STRIDE + k0 + 8];
            }
            #pragma unroll
            for (int mt = 0; mt < 2; mt++)
                #pragma unroll
                for (int nt = 0; nt < 4; nt++) {
                    mma_bf16(acc[mt][nt], Ah[mt], Bh[nt]);
                    mma_bf16(acc[mt][nt], Al[mt], Bh[nt]);
                    mma_bf16(acc[mt][nt], Ah[mt], Bl[nt]);
                }
        }

        // ---- epilogue: gates, c/h update, publish ----
        __nv_bfloat16* hb_hi = &g_hbf[dir][s & 1][0][0][0];
        __nv_bfloat16* hb_lo = &g_hbf[dir][s & 1][1][0][0];
        #pragma unroll
        for (int mt = 0; mt < 2; mt++)
            #pragma unroll
            for (int rr = 0; rr < 2; rr++)
                #pragma unroll
                for (int jb = 0; jb < 2; jb++) {
                    int b = w * 32 + mt * 16 + grp + rr * 8;
                    int j = q * 8 + tig * 2 + jb;
                    int ci = mt * 4 + rr * 2 + jb;
                    int di = rr * 2 + jb;
                    float Gi = acc[mt][0][di];
                    float Gf = acc[mt][1][di];
                    float Gg = acc[mt][2][di];
                    float Go = acc[mt][3][di];
                    float cn = sigm(Gf) * cr[ci] + sigm(Gi) * tanhf(Gg);
                    float hn = sigm(Go) * tanhf(cn);
                    cr[ci] = cn;
                    out[(size_t)t * BATCH * OUT_TB_STRIDE + (size_t)b * OUT_TB_STRIDE
                        + dir * HID + j] = hn;
                    __nv_bfloat16 hh = __float2bfloat16(hn);
                    hb_hi[(size_t)b * HID + j] = hh;
                    hb_lo[(size_t)b * HID + j] = __float2bfloat16(hn - __bfloat162float(hh));
                    if (s == T_STEPS - 1) {
                        float* tail_h = out + OUT_MAIN + dir * 65536;   // hf or hb
                        float* tail_c = tail_h + 32768;                  // cf or cb
                        tail_h[b * HID + j] = hn;
                        tail_c[b * HID + j] = cn;
                    }
                }

        // ---- release ----
        __threadfence();
        __syncthreads();
        if (tid == 0) atomicAdd(&g_bar[dir][s], 1);
    }
}

// ---------------------------------------------------------------------------
extern "C" void kernel_launch(void* const* d_in, const int* in_sizes, int n_in,
                              void* d_out, int out_size)
{
    const float* x     = (const float*)d_in[0];
    const float* h0    = (const float*)d_in[1];
    const float* c0    = (const float*)d_in[2];
    const float* Wih_f = (const float*)d_in[3];
    const float* Whh_f = (const float*)d_in[4];
    const float* bih_f = (const float*)d_in[5];
    const float* bhh_f = (const float*)d_in[6];
    const float* Wih_b = (const float*)d_in[7];
    const float* Whh_b = (const float*)d_in[8];
    const float* bih_b = (const float*)d_in[9];
    const float* bhh_b = (const float*)d_in[10];
    float* out = (float*)d_out;

    static cudaStream_t s_gemm = nullptr;
    static cudaEvent_t ev_fork = nullptr, ev_join = nullptr;
    if (!s_gemm) {
        cudaStreamCreateWithFlags(&s_gemm, cudaStreamNonBlocking);
        cudaEventCreateWithFlags(&ev_fork, cudaEventDisableTiming);
        cudaEventCreateWithFlags(&ev_join, cudaEventDisableTiming);
    }

    cudaFuncSetAttribute(lstm_mma_kernel,
                         cudaFuncAttributeMaxDynamicSharedMemorySize, SMEM_TOTAL);

    init_misc_kernel<<<256, 256>>>(h0);

    // fork: xg gemm runs concurrently, feeding the recurrence per-t
    cudaEventRecord(ev_fork, 0);
    cudaStreamWaitEvent(s_gemm, ev_fork, 0);
    gemm_xg_kernel<<<dim3(16, 512), 256, 0, s_gemm>>>(
        x, Wih_f, Wih_b, bih_f, bhh_f, bih_b, bhh_b);
    cudaEventRecord(ev_join, s_gemm);

    // main stream: persistent HMMA recurrence
    lstm_mma_kernel<<<2 * CTAS_PER_DIR, 128, SMEM_TOTAL>>>(Whh_f, Whh_b, c0, out);

    cudaStreamWaitEvent(0, ev_join, 0);
}